// round 5
// baseline (speedup 1.0000x reference)
#include <cuda_runtime.h>

// SC-based GEMM, collapsed analytically:
//   out[m,n] = sum_k min(t1[m,k], t2[k,n]) * e1[m,k] * e2[k,n]
// t = floor(norm*256), e = sign * 2^{-s} (extra /256 folded into e2).
// Valid because rngSeq = arange(L) and the reference's ascending sequence
// are sorted unary prefixes, so popcount(b1 & b2) == min(t1, t2).
//
// Phase 1: encode each input element once (and zero the output).
// Phase 2: register-blocked (4x4/thread) split-K min-GEMM, RED epilogue.
// BK=16 / ksplit=16 -> 256 blocks, ~2 CTAs/SM co-resident (occupancy fix).

#define MKN 256
#define NEL (MKN * MKN)
#define BM 64            // output tile rows per block
#define BN 64            // output tile cols per block
#define BK 16            // k-chunk per block (ksplit = 256/16 = 16)
#define PAD 2            // float2 pad: row stride 66 float2, 16B aligned

__device__ float2 gEncA[NEL];   // [m][k]  (thr, e)
__device__ float2 gEncB[NEL];   // [k][n]  (thr, e/256)

__device__ __forceinline__ float exp2i(int e) {
    return __int_as_float((127 + e) << 23);   // exact 2^e, e in [-24,24]
}

__device__ __forceinline__ float2 sc_encode(float x, int extra_shift) {
    if (x == 0.0f) return make_float2(0.0f, 0.0f);
    float ax = fabsf(x);
    int q;
    float f = frexpf(ax, &q);                 // ax = f * 2^q, f in [0.5,1)
    int s = (f == 0.5f) ? (1 - q) : (-q);     // floor(-log2(ax)), exact
    s = max(0, min(s, 8));
    float thr = floorf(ax * exp2i(s) * 256.0f);
    float sgn = (x > 0.0f) ? 1.0f : -1.0f;
    return make_float2(thr, sgn * exp2i(-s - extra_shift));
}

__global__ __launch_bounds__(256)
void sc_encode_kernel(const float* __restrict__ A,
                      const float* __restrict__ B,
                      float* __restrict__ out) {
    int i = blockIdx.x * 256 + threadIdx.x;
    gEncA[i] = sc_encode(A[i], 0);
    gEncB[i] = sc_encode(B[i], 8);
    out[i] = 0.0f;                            // epilogue accumulates into out
}

__global__ __launch_bounds__(256)
void sc_gemm_kernel(float* __restrict__ out) {
    __shared__ float2 sA[BK][BM + PAD];       // [k][m]
    __shared__ float2 sB[BK][BN + PAD];       // [k][n]

    const int t  = threadIdx.x;
    const int tx = t & 15;                    // n-group
    const int ty = t >> 4;                    // m-group
    const int m0 = blockIdx.y * BM;
    const int n0 = blockIdx.x * BN;
    const int k0 = blockIdx.z * BK;

    // ---- Fill sA (transpose to [k][m]); 1024 float2 via 512 float4 loads.
    {
        const float4* a4 = (const float4*)gEncA;   // 128 float4 per m-row
        #pragma unroll
        for (int j = 0; j < 2; ++j) {
            int i = t + j * 256;
            int c = i & 7;                    // float4 index within k-chunk
            int m = i >> 3;                   // 0..63
            float4 v = a4[(m0 + m) * 128 + (k0 >> 1) + c];
            sA[2 * c][m]     = make_float2(v.x, v.y);
            sA[2 * c + 1][m] = make_float2(v.z, v.w);
        }
    }
    // ---- Fill sB ([k][n], no transpose); float4 in, float4 out.
    {
        const float4* b4 = (const float4*)gEncB;   // 128 float4 per k-row
        #pragma unroll
        for (int j = 0; j < 2; ++j) {
            int i = t + j * 256;
            int c = i & 31;                   // float4 col within tile (32)
            int k = i >> 5;                   // 0..15
            float4 v = b4[(k0 + k) * 128 + (n0 >> 1) + c];
            *(float4*)&sB[k][2 * c] = v;
        }
    }
    __syncthreads();

    float acc[4][4];
    #pragma unroll
    for (int i = 0; i < 4; ++i)
        #pragma unroll
        for (int j = 0; j < 4; ++j) acc[i][j] = 0.0f;

    #pragma unroll
    for (int k = 0; k < BK; ++k) {
        float2 a[4], b[4];
        *(float4*)&a[0] = *(const float4*)&sA[k][ty * 4];
        *(float4*)&a[2] = *(const float4*)&sA[k][ty * 4 + 2];
        *(float4*)&b[0] = *(const float4*)&sB[k][tx * 4];
        *(float4*)&b[2] = *(const float4*)&sB[k][tx * 4 + 2];
        #pragma unroll
        for (int i = 0; i < 4; ++i)
            #pragma unroll
            for (int j = 0; j < 4; ++j)
                acc[i][j] = fmaf(fminf(a[i].x, b[j].x) * a[i].y, b[j].y,
                                 acc[i][j]);
    }

    #pragma unroll
    for (int i = 0; i < 4; ++i) {
        int m = m0 + ty * 4 + i;
        #pragma unroll
        for (int j = 0; j < 4; ++j)
            atomicAdd(&out[m * MKN + n0 + tx * 4 + j], acc[i][j]);
    }
}

extern "C" void kernel_launch(void* const* d_in, const int* in_sizes, int n_in,
                              void* d_out, int out_size) {
    const float* A = (const float*)d_in[0];   // tensor_1 [256,256]
    const float* B = (const float*)d_in[1];   // tensor_2 [256,256]
    // d_in[2] = rngSeq (arange(256)); sortedness folded into the math.
    float* out = (float*)d_out;

    sc_encode_kernel<<<NEL / 256, 256>>>(A, B, out);
    dim3 grid(MKN / BN, MKN / BM, MKN / BK);  // 4 x 4 x 16 = 256 blocks
    sc_gemm_kernel<<<grid, 256>>>(out);
}